// round 13
// baseline (speedup 1.0000x reference)
#include <cuda_runtime.h>
#include <cstdint>

// Problem constants
//  H=8, KB=8 cells; OB=64, IB=64, K=9, L=9; ZD=64, PD=16, DH=128
//  out: [512, 512, 9, 9] fp32 = 21,233,664 elements

__device__ float g_hid[64 * 128];   // relu(x @ W1^T + b1)
__device__ int   g_ready;           // hid producer arrivals (0..4), reset each launch
__device__ int   g_done;            // block exit count, reset each launch

// Packed f32x2 FMA (sm_103a)
#define FMA_F32X2(d, a, b, c) \
    asm("fma.rn.f32x2 %0, %1, %2, %3;" : "=l"(d) : "l"(a), "l"(b), "l"(c))

__device__ __forceinline__ uint32_t smem_u32(const void* p) {
    uint32_t a;
    asm("{ .reg .u64 t; cvta.to.shared.u64 t, %1; cvt.u32.u64 %0, t; }" : "=r"(a) : "l"(p));
    return a;
}
#define CP_ASYNC16(dst, src) \
    asm volatile("cp.async.cg.shared.global [%0], [%1], 16;" :: "r"(dst), "l"(src))
#define CP_COMMIT() asm volatile("cp.async.commit_group;" ::: "memory")
#define CP_WAIT1()  asm volatile("cp.async.wait_group 1;" ::: "memory")
#define CP_WAIT0()  asm volatile("cp.async.wait_group 0;" ::: "memory")

// ---------------------------------------------------------------------------
// Single fused kernel.
// grid 512: blockIdx.x = ob*8 + ibg ; block 128: cg = tid>>3 (4 cells), ibl = tid&7
//
// Blocks 0..3 additionally compute g_hid (16 rows each) before the main work;
// all blocks spin on g_ready==4. Last exiting block resets flags (replay-safe).
//
// smem pool (floats), dynamic, 54,528 B (13632 floats):
//   hid-producer phase (blocks 0..3): xs_all[16][80] @0
//   GEMM: hs[64][132] @0, wb0[72][36] @8448, wb1[72][36] @11040
//   epilogue: piece[16][648] @0 (41.5KB), 4 pieces (j = 0..3)
// ---------------------------------------------------------------------------
__global__ __launch_bounds__(128)
void fused_all(const float* __restrict__ z_all,
               const float* __restrict__ W1,
               const float* __restrict__ b1,
               const float* __restrict__ pde,
               const float* __restrict__ W2,
               const float* __restrict__ b2,
               const float* __restrict__ unet,
               float* __restrict__ out)
{
    extern __shared__ float sm[];
    float* hs    = sm;               // [64][132]
    float* wb0   = sm + 8448;        // [72][36]
    float* wb1   = sm + 11040;       // [72][36]
    float* piece = sm;               // [16][648] epilogue alias

    const int tid    = threadIdx.x;
    const int ob     = blockIdx.x >> 3;
    const int ibg    = blockIdx.x & 7;
    const int ibbase = ibg * 8;
    const int base9  = (ob * 64 + ibbase) * 9;   // 72 contiguous W2 rows

    const int cg  = tid >> 3;   // cells cg*4 .. cg*4+3
    const int ibl = tid & 7;

    // ============ hid producers: blocks 0..3, 16 rows each ============
    if (blockIdx.x < 4) {
        const int rb = blockIdx.x * 16;
        // stage x rows: xs_all[16][80] = [z_all row (64) | pde (16)]
        for (int idx = tid; idx < 1024; idx += 128) {
            int row = idx >> 6, c = idx & 63;
            sm[row * 80 + c] = z_all[(rb + row) * 64 + c];
        }
        for (int idx = tid; idx < 256; idx += 128) {
            int row = idx >> 4, c = idx & 15;
            sm[row * 80 + 64 + c] = pde[c];
        }
        __syncthreads();
        const float4* wrow = (const float4*)(W1 + tid * 80);
        const float b1j = b1[tid];
#pragma unroll 1
        for (int r = 0; r < 16; ++r) {
            const float* xr = sm + r * 80;
            float a = b1j;
#pragma unroll
            for (int t = 0; t < 20; ++t) {
                float4 w = wrow[t];
                a = fmaf(w.x, xr[4*t+0], a);
                a = fmaf(w.y, xr[4*t+1], a);
                a = fmaf(w.z, xr[4*t+2], a);
                a = fmaf(w.w, xr[4*t+3], a);
            }
            g_hid[(rb + r) * 128 + tid] = fmaxf(a, 0.0f);
        }
        __threadfence();
        __syncthreads();              // all writes done, all xs reads done
        if (tid == 0) atomicAdd(&g_ready, 1);
    }

    // ============ all blocks: wait for hid ============
    if (tid == 0) {
        while (atomicAdd(&g_ready, 0) < 4) __nanosleep(128);
    }
    __syncthreads();

    const uint32_t hs_u  = smem_u32(hs);
    const uint32_t wb0_u = smem_u32(wb0);
    const uint32_t wb1_u = smem_u32(wb1);

    // ---- prologue: async hid (ALL K=128: 32 float4/cell) + W2 chunk0 -> group0
    for (int idx = tid; idx < 2048; idx += 128) {
        int c = idx >> 5, q = idx & 31;
        CP_ASYNC16(hs_u + (uint32_t)(c * 132 + 4 * q) * 4u,
                   (const void*)(g_hid + c * 128 + 4 * q));
    }
    for (int idx = tid; idx < 576; idx += 128) {
        int row = idx >> 3, q = idx & 7;
        CP_ASYNC16(wb0_u + (uint32_t)(row * 36 + 4 * q) * 4u,
                   (const void*)(W2 + (size_t)(base9 + row) * 128 + 4 * q));
    }
    CP_COMMIT();
    for (int idx = tid; idx < 576; idx += 128) {
        int row = idx >> 3, q = idx & 7;
        CP_ASYNC16(wb1_u + (uint32_t)(row * 36 + 4 * q) * 4u,
                   (const void*)(W2 + (size_t)(base9 + row) * 128 + 32 + 4 * q));
    }
    CP_COMMIT();

    unsigned long long acc[4][9];
#pragma unroll
    for (int j = 0; j < 4; ++j)
#pragma unroll
        for (int k = 0; k < 9; ++k) acc[j][k] = 0ull;

    CP_WAIT1();          // group0 done: hs + chunk0 resident
    __syncthreads();

    const float* hp0 = hs + (cg * 4) * 132;
    const float* hp1 = hp0 + 132;
    const float* hp2 = hp0 + 264;
    const float* hp3 = hp0 + 396;

    // ---- GEMM: 4 chunks of 32 d, double buffered ----
#pragma unroll 1
    for (int c = 0; c < 4; ++c) {
        const float* wp = ((c & 1) ? wb1 : wb0) + ibl * 324;
        const int cb = c * 32;
#pragma unroll
        for (int dd = 0; dd < 32; dd += 4) {
            ulonglong2 h0 = *(const ulonglong2*)(hp0 + cb + dd);
            ulonglong2 h1 = *(const ulonglong2*)(hp1 + cb + dd);
            ulonglong2 h2 = *(const ulonglong2*)(hp2 + cb + dd);
            ulonglong2 h3 = *(const ulonglong2*)(hp3 + cb + dd);
#pragma unroll
            for (int k = 0; k < 9; ++k) {
                ulonglong2 w = *(const ulonglong2*)(wp + k * 36 + dd);
                FMA_F32X2(acc[0][k], h0.x, w.x, acc[0][k]);
                FMA_F32X2(acc[0][k], h0.y, w.y, acc[0][k]);
                FMA_F32X2(acc[1][k], h1.x, w.x, acc[1][k]);
                FMA_F32X2(acc[1][k], h1.y, w.y, acc[1][k]);
                FMA_F32X2(acc[2][k], h2.x, w.x, acc[2][k]);
                FMA_F32X2(acc[2][k], h2.y, w.y, acc[2][k]);
                FMA_F32X2(acc[3][k], h3.x, w.x, acc[3][k]);
                FMA_F32X2(acc[3][k], h3.y, w.y, acc[3][k]);
            }
        }
        __syncthreads();
        if (c < 2) {
            uint32_t bu = (c & 1) ? wb1_u : wb0_u;
            const float* src = W2 + (c + 2) * 32;
            for (int idx = tid; idx < 576; idx += 128) {
                int row = idx >> 3, q = idx & 7;
                CP_ASYNC16(bu + (uint32_t)(row * 36 + 4 * q) * 4u,
                           (const void*)(src + (size_t)(base9 + row) * 128 + 4 * q));
            }
            CP_COMMIT();
            CP_WAIT1();
        } else if (c == 2) {
            CP_WAIT0();
        }
        if (c < 3) __syncthreads();
    }
    __syncthreads();   // GEMM smem no longer needed; piece aliases it

    // ============ epilogue: register-sourced outer products ============
    // bias for this thread's 9 cols (independent of cell)
    float bv[9];
#pragma unroll
    for (int k = 0; k < 9; ++k) bv[k] = b2[base9 + ibl * 9 + k];

    // unet prefetch for j=0
    float ucur[9];
    {
        int cell = cg * 4;                         // j = 0
        int h = cell >> 3, kb = cell & 7;
        const float* up = unet +
            ((size_t)(h * 64 + ob) * 512 + kb * 64 + ibbase + ibl) * 9;
#pragma unroll
        for (int l = 0; l < 9; ++l) ucur[l] = up[l];
    }

#pragma unroll 1
    for (int j = 0; j < 4; ++j) {
        float unext[9];
        if (j < 3) {
            int celln = cg * 4 + j + 1;
            int hn = celln >> 3, kbn = celln & 7;
            const float* up = unet +
                ((size_t)(hn * 64 + ob) * 512 + kbn * 64 + ibbase + ibl) * 9;
#pragma unroll
            for (int l = 0; l < 9; ++l) unext[l] = up[l];
        }

        // finalize this cell's 9 exe values from accumulators
        float e[9];
#pragma unroll
        for (int k = 0; k < 9; ++k) {
            float2 p = *(float2*)&acc[j][k];
            e[k] = p.x + p.y + bv[k];
        }

        // 81 products -> piece[cg][ibl*81 + k*9 + l]  (conflict-free scalar STS)
        float* pp = piece + cg * 648 + ibl * 81;
#pragma unroll
        for (int k = 0; k < 9; ++k)
#pragma unroll
            for (int l = 0; l < 9; ++l)
                pp[k * 9 + l] = e[k] * ucur[l];

        __syncthreads();

        // copy-out: 2592 aligned float4 (16 cell-chunks of 648 contiguous floats)
        {
            int cgi = 0, r = tid;     // r = float4 index within the 162-float4 chunk
            while (cgi < 16) {
                int cell2 = cgi * 4 + j;
                int h2 = cell2 >> 3, kb2 = cell2 & 7;
                size_t gbase =
                    ((size_t)(h2 * 64 + ob) * 512 + kb2 * 64 + ibbase) * 81;
                float4 v = *(const float4*)(piece + cgi * 648 + 4 * r);
                __stcs((float4*)(out + gbase + 4 * r), v);
                r += 128;
                if (r >= 162) { r -= 162; ++cgi; }
            }
        }
        __syncthreads();   // piece free for next j

#pragma unroll
        for (int l = 0; l < 9; ++l) ucur[l] = unext[l];
    }

    // ============ exit: last block resets flags for next replay ============
    if (tid == 0) {
        __threadfence();
        int n = atomicAdd(&g_done, 1);
        if (n == 511) {
            g_ready = 0;
            g_done  = 0;
            __threadfence();
        }
    }
}

// ---------------------------------------------------------------------------
extern "C" void kernel_launch(void* const* d_in, const int* in_sizes, int n_in,
                              void* d_out, int out_size)
{
    const float* z_all = (const float*)d_in[0];   // [64, 64]
    const float* W1    = (const float*)d_in[1];   // [128, 80]
    const float* b1    = (const float*)d_in[2];   // [128]
    const float* W2    = (const float*)d_in[3];   // [36864, 128]
    const float* b2    = (const float*)d_in[4];   // [36864]
    const float* unet  = (const float*)d_in[5];   // [512, 512, 9]
    const float* pde   = (const float*)d_in[6];   // [16]
    float* out = (float*)d_out;                   // [512, 512, 9, 9]

    cudaFuncSetAttribute(fused_all,
                         cudaFuncAttributeMaxDynamicSharedMemorySize, 54528);

    fused_all<<<512, 128, 54528>>>(z_all, W1, b1, pde, W2, b2, unet, out);
}